// round 8
// baseline (speedup 1.0000x reference)
#include <cuda_runtime.h>
#include <cuda_bf16.h>
#include <math.h>
#include <stdint.h>

// Problem constants (fixed by reference)
#define NN   100000
#define EE   1600000
#define MPAD 100096   // 782 * 128

// ---------------------------------------------------------------------------
// Scratch (__device__ globals; no runtime allocation)
// ---------------------------------------------------------------------------
__device__ float         g_gout[(size_t)MPAD * 256];   // GEMM fp32 output / SpMM input
__device__ __nv_bfloat16 g_ah[(size_t)MPAD * 256];     // activation hi (bf16)
__device__ __nv_bfloat16 g_al[(size_t)MPAD * 256];     // activation lo (bf16)
__device__ __nv_bfloat16 g_wh[3 * 256 * 256];          // W^T hi per layer (n-major, k contig)
__device__ __nv_bfloat16 g_wl[3 * 256 * 256];          // W^T lo per layer
__device__ int   g_deg[NN];
__device__ float g_dinv[NN];
__device__ int   g_rowptr[NN + 1];
__device__ int   g_cursor[NN];
__device__ int   g_bsum[128];
__device__ int2  g_edges[EE];                          // packed (src, norm-bits)

// ---------------------------------------------------------------------------
// PTX helpers (sm_80-era; valid on plain compute_100 target)
// ---------------------------------------------------------------------------
__device__ __forceinline__ uint32_t smem_u32(const void* p) {
    uint32_t a;
    asm("{ .reg .u64 t; cvta.to.shared.u64 t, %1; cvt.u32.u64 %0, t; }"
        : "=r"(a) : "l"(p));
    return a;
}

#define CP16(smem_addr, gptr) \
    asm volatile("cp.async.cg.shared.global [%0], [%1], 16;" \
        :: "r"(smem_addr), "l"(gptr) : "memory")
#define CP_COMMIT() asm volatile("cp.async.commit_group;" ::: "memory")
#define CP_WAIT2()  asm volatile("cp.async.wait_group 2;" ::: "memory")

#define LDSM4(r0, r1, r2, r3, addr) \
    asm volatile("ldmatrix.sync.aligned.m8n8.x4.shared.b16 {%0,%1,%2,%3}, [%4];" \
        : "=r"(r0), "=r"(r1), "=r"(r2), "=r"(r3) : "r"(addr))

#define MMA16816(d, a, b) \
    asm volatile("mma.sync.aligned.m16n8k16.row.col.f32.bf16.bf16.f32 " \
        "{%0,%1,%2,%3},{%4,%5,%6,%7},{%8,%9},{%0,%1,%2,%3};" \
        : "+f"((d)[0]), "+f"((d)[1]), "+f"((d)[2]), "+f"((d)[3]) \
        : "r"((a)[0]), "r"((a)[1]), "r"((a)[2]), "r"((a)[3]), \
          "r"((b)[0]), "r"((b)[1]))

// ---------------------------------------------------------------------------
// bf16 hi/lo split helper
// ---------------------------------------------------------------------------
__device__ __forceinline__ void split4(float4 v, __nv_bfloat16* ph, __nv_bfloat16* pl) {
    __nv_bfloat162 h0 = __floats2bfloat162_rn(v.x, v.y);
    __nv_bfloat162 h1 = __floats2bfloat162_rn(v.z, v.w);
    float2 f0 = __bfloat1622float2(h0);
    float2 f1 = __bfloat1622float2(h1);
    __nv_bfloat162 l0 = __floats2bfloat162_rn(v.x - f0.x, v.y - f0.y);
    __nv_bfloat162 l1 = __floats2bfloat162_rn(v.z - f1.x, v.w - f1.y);
    *(__nv_bfloat162*)(ph)     = h0;
    *(__nv_bfloat162*)(ph + 2) = h1;
    *(__nv_bfloat162*)(pl)     = l0;
    *(__nv_bfloat162*)(pl + 2) = l1;
}

// ---------------------------------------------------------------------------
// k_prep: fused zero(g_deg) + wsplit + xsplit (independent jobs)
// blocks [0,391): zero; [391,1159): wsplit; [1159,26159): xsplit
// ---------------------------------------------------------------------------
__global__ void __launch_bounds__(256) k_prep(const float* __restrict__ x,
                                             const float* __restrict__ W1,
                                             const float* __restrict__ W2,
                                             const float* __restrict__ W3) {
    int bid = blockIdx.x;
    if (bid < 391) {
        int i = bid * 256 + threadIdx.x;
        if (i < NN) g_deg[i] = 0;
    } else if (bid < 1159) {
        int idx = (bid - 391) * 256 + threadIdx.x;   // 0..196607
        int l = idx >> 16;
        int r = idx & 65535;
        int k = r >> 8, n = r & 255;
        const float* W = (l == 0) ? W1 : ((l == 1) ? W2 : W3);
        float v = W[k * 256 + n];
        __nv_bfloat16 hi = __float2bfloat16(v);
        g_wh[l * 65536 + n * 256 + k] = hi;
        g_wl[l * 65536 + n * 256 + k] = __float2bfloat16(v - __bfloat162float(hi));
    } else {
        size_t i = (size_t)(bid - 1159) * 256 + threadIdx.x;   // float4 index
        if (i < (size_t)NN * 64) {
            float4 v = ((const float4*)x)[i];
            split4(v, g_ah + i * 4, g_al + i * 4);
        }
    }
}

// ---------------------------------------------------------------------------
// Scan chain (unchanged)
// ---------------------------------------------------------------------------
__global__ void k_scan1() {
    __shared__ int sh[1024];
    int i = blockIdx.x * 1024 + threadIdx.x;
    int v = (i < NN) ? g_deg[i] : 0;
    if (i < NN) g_dinv[i] = rsqrtf((float)v + 1.0f);
    sh[threadIdx.x] = v;
    __syncthreads();
    #pragma unroll
    for (int off = 1; off < 1024; off <<= 1) {
        int t = (threadIdx.x >= off) ? sh[threadIdx.x - off] : 0;
        __syncthreads();
        sh[threadIdx.x] += t;
        __syncthreads();
    }
    if (i < NN) g_rowptr[i] = sh[threadIdx.x] - v;
    if (threadIdx.x == 1023) g_bsum[blockIdx.x] = sh[1023];
}

__global__ void k_scan2() {
    __shared__ int sh[128];
    const int NB = (NN + 1023) / 1024;
    int v = (threadIdx.x < NB) ? g_bsum[threadIdx.x] : 0;
    sh[threadIdx.x] = v;
    __syncthreads();
    #pragma unroll
    for (int off = 1; off < 128; off <<= 1) {
        int t = (threadIdx.x >= off) ? sh[threadIdx.x - off] : 0;
        __syncthreads();
        sh[threadIdx.x] += t;
        __syncthreads();
    }
    g_bsum[threadIdx.x] = sh[threadIdx.x] - v;
}

__global__ void k_scan3() {
    int i = blockIdx.x * 1024 + threadIdx.x;
    if (i < NN) {
        g_rowptr[i] += g_bsum[blockIdx.x];
        g_cursor[i] = 0;
    }
    if (i == 0) g_rowptr[NN] = EE;
}

__global__ void k_scatter(const int* __restrict__ ei) {
    int e = blockIdx.x * blockDim.x + threadIdx.x;
    if (e >= EE) return;
    int s = ei[e];
    int d = ei[EE + e];
    int pos = g_rowptr[d] + atomicAdd(&g_cursor[d], 1);
    g_edges[pos] = make_int2(s, __float_as_int(g_dinv[s] * g_dinv[d]));
}

// ---------------------------------------------------------------------------
// GEMM body (bf16 split 3-term via mma.sync), shared by k_mgemm / k_mgemm_hist.
// gid in [0, 1564): ncol0 = (gid&1)*128, row0 = (gid>>1)*128.
// ---------------------------------------------------------------------------
#define MG_STAGE 24576u
#define MG_SMEM  98304
#define MG_BLOCKS 1564

__device__ __forceinline__ void mgemm_body(char* smem, int gid,
                                           const __nv_bfloat16* __restrict__ Wh,
                                           const __nv_bfloat16* __restrict__ Wl) {
    const uint32_t sb = smem_u32(smem);

    const int tid  = threadIdx.x;
    const int wid  = tid >> 5;
    const int lane = tid & 31;
    const int wm   = wid >> 1;          // 0..3
    const int wn   = wid & 1;           // 0..1
    const int    ncol0 = (gid & 1) * 128;
    const size_t row0  = (size_t)(gid >> 1) * 128;

    const int gr = tid >> 1;            // 0..127 (row / ncol)
    const int gk = (tid & 1) * 8;       // bf16 k offset within 16
    const size_t gA = (row0 + gr) * 256 + gk;
    const size_t gB = ((size_t)(ncol0 + gr)) * 256 + gk;
    const uint32_t sOff = (uint32_t)(gr * 48 + gk * 2);

    const int lr = lane & 7;
    const uint32_t offA = (uint32_t)((wm * 32 + lr + ((lane >> 3) & 1) * 8) * 48
                                     + ((lane >> 4) & 1) * 16);
    const uint32_t offB = (uint32_t)((wn * 64 + lr + ((lane >> 4) & 1) * 8) * 48
                                     + ((lane >> 3) & 1) * 16);

    float acc[2][8][4];
    #pragma unroll
    for (int i = 0; i < 2; i++)
        #pragma unroll
        for (int j = 0; j < 8; j++)
            #pragma unroll
            for (int q = 0; q < 4; q++) acc[i][j][q] = 0.f;

    #pragma unroll
    for (int p = 0; p < 3; p++) {
        const uint32_t bo = (uint32_t)p * MG_STAGE;
        const size_t kk = (size_t)p * 16;
        CP16(sb + bo + sOff,          g_ah + gA + kk);
        CP16(sb + bo + 6144u + sOff,  g_al + gA + kk);
        CP16(sb + bo + 12288u + sOff, Wh + gB + kk);
        CP16(sb + bo + 18432u + sOff, Wl + gB + kk);
        CP_COMMIT();
    }

    for (int c = 0; c < 16; c++) {
        CP_WAIT2();
        __syncthreads();

        if (c + 3 < 16) {
            const uint32_t bo = (uint32_t)((c + 3) & 3) * MG_STAGE;
            const size_t kk = (size_t)(c + 3) * 16;
            CP16(sb + bo + sOff,          g_ah + gA + kk);
            CP16(sb + bo + 6144u + sOff,  g_al + gA + kk);
            CP16(sb + bo + 12288u + sOff, Wh + gB + kk);
            CP16(sb + bo + 18432u + sOff, Wl + gB + kk);
        }
        CP_COMMIT();

        const uint32_t base  = sb + (uint32_t)(c & 3) * MG_STAGE;
        const uint32_t aBase = base + offA;
        const uint32_t bBase = base + 12288u + offB;

        uint32_t ah[2][4], al[2][4], bh[8][2], bl[8][2];
        #pragma unroll
        for (int mi = 0; mi < 2; mi++) {
            LDSM4(ah[mi][0], ah[mi][1], ah[mi][2], ah[mi][3], aBase + mi * 768u);
            LDSM4(al[mi][0], al[mi][1], al[mi][2], al[mi][3], aBase + 6144u + mi * 768u);
        }
        #pragma unroll
        for (int j = 0; j < 4; j++) {
            uint32_t t0, t1, t2, t3;
            LDSM4(t0, t1, t2, t3, bBase + j * 768u);
            bh[2 * j][0] = t0; bh[2 * j][1] = t1;
            bh[2 * j + 1][0] = t2; bh[2 * j + 1][1] = t3;
            LDSM4(t0, t1, t2, t3, bBase + 6144u + j * 768u);
            bl[2 * j][0] = t0; bl[2 * j][1] = t1;
            bl[2 * j + 1][0] = t2; bl[2 * j + 1][1] = t3;
        }

        #pragma unroll
        for (int mi = 0; mi < 2; mi++)
            #pragma unroll
            for (int nj = 0; nj < 8; nj++) {
                MMA16816(acc[mi][nj], ah[mi], bh[nj]);
                MMA16816(acc[mi][nj], ah[mi], bl[nj]);
                MMA16816(acc[mi][nj], al[mi], bh[nj]);
            }
    }

    #pragma unroll
    for (int mi = 0; mi < 2; mi++) {
        const size_t r0 = row0 + wm * 32 + mi * 16 + (lane >> 2);
        const int cc0 = ncol0 + wn * 64 + (lane & 3) * 2;
        #pragma unroll
        for (int nj = 0; nj < 8; nj++) {
            const int cc = cc0 + nj * 8;
            if (r0 < NN)
                *(float2*)&g_gout[r0 * 256 + cc] =
                    make_float2(acc[mi][nj][0], acc[mi][nj][1]);
            if (r0 + 8 < NN)
                *(float2*)&g_gout[(r0 + 8) * 256 + cc] =
                    make_float2(acc[mi][nj][2], acc[mi][nj][3]);
        }
    }
}

// GEMM-only kernel (layers 2, 3); 1-D grid of MG_BLOCKS
__global__ void __launch_bounds__(256, 2) k_mgemm(int lidx) {
    extern __shared__ char smem[];
    mgemm_body(smem, blockIdx.x,
               g_wh + (size_t)lidx * 65536, g_wl + (size_t)lidx * 65536);
}

// Layer-1 GEMM merged with degree histogram.
// Grid = 2*MG_BLOCKS - 1 = 3127: even bids -> GEMM tile (bid>>1),
// odd bids -> histogram chunk (bid>>1)*1024 edges (1563 chunks >= EE/1024).
__global__ void __launch_bounds__(256, 2) k_mgemm_hist(const int* __restrict__ ei) {
    extern __shared__ char smem[];
    int bid = blockIdx.x;
    if (bid & 1) {
        int base = (bid >> 1) * 1024 + threadIdx.x;
        #pragma unroll
        for (int it = 0; it < 4; it++) {
            int e = base + it * 256;
            if (e < EE) atomicAdd(&g_deg[ei[EE + e]], 1);
        }
        return;
    }
    mgemm_body(smem, bid >> 1, g_wh, g_wl);
}

// ---------------------------------------------------------------------------
// SpMM (F=256): agg = sum_e norm * H[src] + dinv^2 * H[n] + bias, relu,
// writes bf16 hi/lo splits for the next GEMM. Gather loop unrolled 4x.
// ---------------------------------------------------------------------------
__global__ void __launch_bounds__(256) k_spmm256(const float* __restrict__ bias) {
    const float* __restrict__ H = g_gout;

    int warp = threadIdx.x >> 5;
    int lane = threadIdx.x & 31;
    int node = blockIdx.x * 8 + warp;
    if (node >= NN) return;

    int beg = g_rowptr[node];
    int end = g_rowptr[node + 1];

    float4 acc0 = make_float4(0.f, 0.f, 0.f, 0.f);
    float4 acc1 = make_float4(0.f, 0.f, 0.f, 0.f);

    int e = beg;
    for (; e + 3 < end; e += 4) {
        int2 p0 = g_edges[e];
        int2 p1 = g_edges[e + 1];
        int2 p2 = g_edges[e + 2];
        int2 p3 = g_edges[e + 3];
        float w0 = __int_as_float(p0.y);
        float w1 = __int_as_float(p1.y);
        float w2 = __int_as_float(p2.y);
        float w3 = __int_as_float(p3.y);
        const float4* hp0 = (const float4*)(H + (size_t)p0.x * 256);
        const float4* hp1 = (const float4*)(H + (size_t)p1.x * 256);
        const float4* hp2 = (const float4*)(H + (size_t)p2.x * 256);
        const float4* hp3 = (const float4*)(H + (size_t)p3.x * 256);
        float4 a0 = hp0[lane];
        float4 a1 = hp1[lane];
        float4 a2 = hp2[lane];
        float4 a3 = hp3[lane];
        float4 b0 = hp0[lane + 32];
        float4 b1 = hp1[lane + 32];
        float4 b2 = hp2[lane + 32];
        float4 b3 = hp3[lane + 32];
        acc0.x += w0 * a0.x + w1 * a1.x + w2 * a2.x + w3 * a3.x;
        acc0.y += w0 * a0.y + w1 * a1.y + w2 * a2.y + w3 * a3.y;
        acc0.z += w0 * a0.z + w1 * a1.z + w2 * a2.z + w3 * a3.z;
        acc0.w += w0 * a0.w + w1 * a1.w + w2 * a2.w + w3 * a3.w;
        acc1.x += w0 * b0.x + w1 * b1.x + w2 * b2.x + w3 * b3.x;
        acc1.y += w0 * b0.y + w1 * b1.y + w2 * b2.y + w3 * b3.y;
        acc1.z += w0 * b0.z + w1 * b1.z + w2 * b2.z + w3 * b3.z;
        acc1.w += w0 * b0.w + w1 * b1.w + w2 * b2.w + w3 * b3.w;
    }
    for (; e < end; e++) {
        int2 p = g_edges[e];
        float w = __int_as_float(p.y);
        const float4* hp = (const float4*)(H + (size_t)p.x * 256);
        float4 a = hp[lane];
        float4 b = hp[lane + 32];
        acc0.x += w * a.x; acc0.y += w * a.y; acc0.z += w * a.z; acc0.w += w * a.w;
        acc1.x += w * b.x; acc1.y += w * b.y; acc1.z += w * b.z; acc1.w += w * b.w;
    }

    float di = g_dinv[node];
    float w2 = di * di;
    {
        const float4* hp = (const float4*)(H + (size_t)node * 256);
        float4 a = hp[lane];
        float4 b = hp[lane + 32];
        acc0.x += w2 * a.x; acc0.y += w2 * a.y; acc0.z += w2 * a.z; acc0.w += w2 * a.w;
        acc1.x += w2 * b.x; acc1.y += w2 * b.y; acc1.z += w2 * b.z; acc1.w += w2 * b.w;
    }

    const float4* bb = (const float4*)bias;
    float4 b0 = bb[lane];
    float4 b1 = bb[lane + 32];
    acc0.x = fmaxf(acc0.x + b0.x, 0.f); acc0.y = fmaxf(acc0.y + b0.y, 0.f);
    acc0.z = fmaxf(acc0.z + b0.z, 0.f); acc0.w = fmaxf(acc0.w + b0.w, 0.f);
    acc1.x = fmaxf(acc1.x + b1.x, 0.f); acc1.y = fmaxf(acc1.y + b1.y, 0.f);
    acc1.z = fmaxf(acc1.z + b1.z, 0.f); acc1.w = fmaxf(acc1.w + b1.w, 0.f);

    size_t base = (size_t)node * 256 + lane * 4;
    split4(acc0, g_ah + base,       g_al + base);
    split4(acc1, g_ah + base + 128, g_al + base + 128);
}

// ---------------------------------------------------------------------------
// GEMM (N=16): g_gout[M x 16] = (g_ah+g_al)[M x 256] @ W4[256 x 16]
// ---------------------------------------------------------------------------
__global__ void __launch_bounds__(256) k_gemm16(const float* __restrict__ W) {
    __shared__ float Ws[256 * 16];
    for (int i = threadIdx.x; i < 256 * 16; i += 256) Ws[i] = W[i];
    __syncthreads();

    int r = blockIdx.x * 16 + (threadIdx.x >> 4);
    int c = threadIdx.x & 15;
    if (r >= NN) return;

    const __nv_bfloat162* ah = (const __nv_bfloat162*)(g_ah + (size_t)r * 256);
    const __nv_bfloat162* al = (const __nv_bfloat162*)(g_al + (size_t)r * 256);
    float acc = 0.f;
    #pragma unroll 16
    for (int k2 = 0; k2 < 128; k2++) {
        float2 h = __bfloat1622float2(ah[k2]);
        float2 l = __bfloat1622float2(al[k2]);
        acc += (h.x + l.x) * Ws[(2 * k2) * 16 + c];
        acc += (h.y + l.y) * Ws[(2 * k2 + 1) * 16 + c];
    }
    g_gout[(size_t)r * 16 + c] = acc;
}

// ---------------------------------------------------------------------------
// SpMM (F=16) + bias + log_softmax -> final output
// ---------------------------------------------------------------------------
__global__ void __launch_bounds__(256) k_spmm16(const float* __restrict__ bias,
                                               float* __restrict__ out) {
    const float* __restrict__ H = g_gout;

    int warp = threadIdx.x >> 5;
    int lane = threadIdx.x & 31;
    int node = blockIdx.x * 8 + warp;
    if (node >= NN) return;

    int f = lane & 15;
    int beg = g_rowptr[node];
    int end = g_rowptr[node + 1];

    float acc = 0.f;
    for (int e = beg; e < end; e++) {
        int2 p = g_edges[e];
        acc += __int_as_float(p.y) * H[(size_t)p.x * 16 + f];
    }
    float di = g_dinv[node];
    acc += di * di * H[(size_t)node * 16 + f];
    acc += bias[f];

    float m = acc;
    #pragma unroll
    for (int o = 8; o > 0; o >>= 1)
        m = fmaxf(m, __shfl_xor_sync(0xffffffffu, m, o, 16));
    float ex = expf(acc - m);
    float s = ex;
    #pragma unroll
    for (int o = 8; o > 0; o >>= 1)
        s += __shfl_xor_sync(0xffffffffu, s, o, 16);

    if (lane < 16)
        out[(size_t)node * 16 + f] = (acc - m) - logf(s);
}

// ---------------------------------------------------------------------------
// Launcher — single stream; hist hidden under GEMM L1 via merged kernel
// ---------------------------------------------------------------------------
extern "C" void kernel_launch(void* const* d_in, const int* in_sizes, int n_in,
                              void* d_out, int out_size)
{
    const float* x  = (const float*)d_in[0];
    const int*   ei = (const int*)  d_in[1];
    const float* W1 = (const float*)d_in[2];
    const float* b1 = (const float*)d_in[3];
    const float* W2 = (const float*)d_in[4];
    const float* b2 = (const float*)d_in[5];
    const float* W3 = (const float*)d_in[6];
    const float* b3 = (const float*)d_in[7];
    const float* W4 = (const float*)d_in[8];
    const float* b4 = (const float*)d_in[9];
    float* out = (float*)d_out;

    static int s_attr_done = 0;
    if (!s_attr_done) {
        cudaFuncSetAttribute(k_mgemm, cudaFuncAttributeMaxDynamicSharedMemorySize, MG_SMEM);
        cudaFuncSetAttribute(k_mgemm_hist, cudaFuncAttributeMaxDynamicSharedMemorySize, MG_SMEM);
        s_attr_done = 1;
    }

    const int NB_SCAN = (NN + 1023) / 1024;   // 98
    const int sgrid = (NN + 7) / 8;           // 12500

    // prep: zero(g_deg) + weight split + x split (independent, one kernel)
    k_prep<<<26159, 256>>>(x, W1, W2, W3);

    // layer-1 GEMM with histogram blocks interleaved (hist hides under GEMM)
    k_mgemm_hist<<<2 * MG_BLOCKS - 1, 256, MG_SMEM>>>(ei);

    // CSR build (depends on hist)
    k_scan1  <<<NB_SCAN, 1024>>>();
    k_scan2  <<<1, 128>>>();
    k_scan3  <<<NB_SCAN, 1024>>>();
    k_scatter<<<(EE + 255) / 256, 256>>>(ei);

    // layer 1 aggregate
    k_spmm256<<<sgrid, 256>>>(b1);
    // layer 2
    k_mgemm  <<<MG_BLOCKS, 256, MG_SMEM>>>(1);
    k_spmm256<<<sgrid, 256>>>(b2);
    // layer 3
    k_mgemm  <<<MG_BLOCKS, 256, MG_SMEM>>>(2);
    k_spmm256<<<sgrid, 256>>>(b3);
    // layer 4
    k_gemm16 <<<(NN + 15) / 16, 256>>>(W4);
    k_spmm16 <<<sgrid, 256>>>(b4, out);
}

// round 9
// speedup vs baseline: 1.1163x; 1.1163x over previous
#include <cuda_runtime.h>
#include <cuda_bf16.h>
#include <math.h>
#include <stdint.h>

// Problem constants (fixed by reference)
#define NN   100000
#define EE   1600000
#define MPAD 100096   // 782 * 128

// ---------------------------------------------------------------------------
// Scratch (__device__ globals; no runtime allocation)
// ---------------------------------------------------------------------------
__device__ float         g_gout[(size_t)MPAD * 256];   // GEMM fp32 output / SpMM input
__device__ __nv_bfloat16 g_ah[(size_t)MPAD * 256];     // activation hi (bf16)
__device__ __nv_bfloat16 g_al[(size_t)MPAD * 256];     // activation lo (bf16)
__device__ __nv_bfloat16 g_wh[3 * 256 * 256];          // W^T hi per layer (n-major, k contig)
__device__ __nv_bfloat16 g_wl[3 * 256 * 256];          // W^T lo per layer
__device__ float         g_h4[(size_t)NN * 16];        // fused layer-4 pre-agg
__device__ int   g_deg[NN];
__device__ float g_dinv[NN];
__device__ int   g_rowptr[NN + 1];
__device__ int   g_cursor[NN];
__device__ int   g_bsum[128];
__device__ int2  g_edges[EE];                          // packed (src, norm-bits)

// ---------------------------------------------------------------------------
// PTX helpers (sm_80-era; valid on plain compute_100 target)
// ---------------------------------------------------------------------------
__device__ __forceinline__ uint32_t smem_u32(const void* p) {
    uint32_t a;
    asm("{ .reg .u64 t; cvta.to.shared.u64 t, %1; cvt.u32.u64 %0, t; }"
        : "=r"(a) : "l"(p));
    return a;
}

#define CP16(smem_addr, gptr) \
    asm volatile("cp.async.cg.shared.global [%0], [%1], 16;" \
        :: "r"(smem_addr), "l"(gptr) : "memory")
#define CP_COMMIT() asm volatile("cp.async.commit_group;" ::: "memory")
#define CP_WAIT2()  asm volatile("cp.async.wait_group 2;" ::: "memory")

#define LDSM4(r0, r1, r2, r3, addr) \
    asm volatile("ldmatrix.sync.aligned.m8n8.x4.shared.b16 {%0,%1,%2,%3}, [%4];" \
        : "=r"(r0), "=r"(r1), "=r"(r2), "=r"(r3) : "r"(addr))

#define MMA16816(d, a, b) \
    asm volatile("mma.sync.aligned.m16n8k16.row.col.f32.bf16.bf16.f32 " \
        "{%0,%1,%2,%3},{%4,%5,%6,%7},{%8,%9},{%0,%1,%2,%3};" \
        : "+f"((d)[0]), "+f"((d)[1]), "+f"((d)[2]), "+f"((d)[3]) \
        : "r"((a)[0]), "r"((a)[1]), "r"((a)[2]), "r"((a)[3]), \
          "r"((b)[0]), "r"((b)[1]))

// ---------------------------------------------------------------------------
// bf16 hi/lo split helper
// ---------------------------------------------------------------------------
__device__ __forceinline__ void split4(float4 v, __nv_bfloat16* ph, __nv_bfloat16* pl) {
    __nv_bfloat162 h0 = __floats2bfloat162_rn(v.x, v.y);
    __nv_bfloat162 h1 = __floats2bfloat162_rn(v.z, v.w);
    float2 f0 = __bfloat1622float2(h0);
    float2 f1 = __bfloat1622float2(h1);
    __nv_bfloat162 l0 = __floats2bfloat162_rn(v.x - f0.x, v.y - f0.y);
    __nv_bfloat162 l1 = __floats2bfloat162_rn(v.z - f1.x, v.w - f1.y);
    *(__nv_bfloat162*)(ph)     = h0;
    *(__nv_bfloat162*)(ph + 2) = h1;
    *(__nv_bfloat162*)(pl)     = l0;
    *(__nv_bfloat162*)(pl + 2) = l1;
}

// ---------------------------------------------------------------------------
// Graph preprocessing
// ---------------------------------------------------------------------------
__global__ void k_zero() {
    int i = blockIdx.x * blockDim.x + threadIdx.x;
    if (i < NN) g_deg[i] = 0;
}

__global__ void k_hist(const int* __restrict__ ei) {
    int e = blockIdx.x * blockDim.x + threadIdx.x;
    if (e < EE) atomicAdd(&g_deg[ei[EE + e]], 1);
}

__global__ void k_scan1() {
    __shared__ int sh[1024];
    int i = blockIdx.x * 1024 + threadIdx.x;
    int v = (i < NN) ? g_deg[i] : 0;
    if (i < NN) g_dinv[i] = rsqrtf((float)v + 1.0f);
    sh[threadIdx.x] = v;
    __syncthreads();
    #pragma unroll
    for (int off = 1; off < 1024; off <<= 1) {
        int t = (threadIdx.x >= off) ? sh[threadIdx.x - off] : 0;
        __syncthreads();
        sh[threadIdx.x] += t;
        __syncthreads();
    }
    if (i < NN) g_rowptr[i] = sh[threadIdx.x] - v;
    if (threadIdx.x == 1023) g_bsum[blockIdx.x] = sh[1023];
}

__global__ void k_scan2() {
    __shared__ int sh[128];
    const int NB = (NN + 1023) / 1024;
    int v = (threadIdx.x < NB) ? g_bsum[threadIdx.x] : 0;
    sh[threadIdx.x] = v;
    __syncthreads();
    #pragma unroll
    for (int off = 1; off < 128; off <<= 1) {
        int t = (threadIdx.x >= off) ? sh[threadIdx.x - off] : 0;
        __syncthreads();
        sh[threadIdx.x] += t;
        __syncthreads();
    }
    g_bsum[threadIdx.x] = sh[threadIdx.x] - v;
}

__global__ void k_scan3() {
    int i = blockIdx.x * 1024 + threadIdx.x;
    if (i < NN) {
        g_rowptr[i] += g_bsum[blockIdx.x];
        g_cursor[i] = 0;
    }
    if (i == 0) g_rowptr[NN] = EE;
}

__global__ void k_scatter(const int* __restrict__ ei) {
    int e = blockIdx.x * blockDim.x + threadIdx.x;
    if (e >= EE) return;
    int s = ei[e];
    int d = ei[EE + e];
    int pos = g_rowptr[d] + atomicAdd(&g_cursor[d], 1);
    g_edges[pos] = make_int2(s, __float_as_int(g_dinv[s] * g_dinv[d]));
}

// ---------------------------------------------------------------------------
// Weight transpose + bf16 split: Wh/Wl[n*256+k] from W[k*256+n]
// ---------------------------------------------------------------------------
__global__ void k_wsplit(const float* __restrict__ W1, const float* __restrict__ W2,
                         const float* __restrict__ W3) {
    int idx = blockIdx.x * 256 + threadIdx.x;   // 0..196607
    int l = idx >> 16;
    int r = idx & 65535;
    int k = r >> 8, n = r & 255;
    const float* W = (l == 0) ? W1 : ((l == 1) ? W2 : W3);
    float v = W[k * 256 + n];
    __nv_bfloat16 hi = __float2bfloat16(v);
    g_wh[l * 65536 + n * 256 + k] = hi;
    g_wl[l * 65536 + n * 256 + k] = __float2bfloat16(v - __bfloat162float(hi));
}

// x (fp32) -> g_ah/g_al (bf16 hi/lo)
__global__ void k_xsplit(const float* __restrict__ x) {
    size_t i = (size_t)blockIdx.x * blockDim.x + threadIdx.x;   // float4 index
    if (i >= (size_t)NN * 64) return;
    float4 v = ((const float4*)x)[i];
    split4(v, g_ah + i * 4, g_al + i * 4);
}

// ---------------------------------------------------------------------------
// Tensor GEMM via mma.sync (bf16 split 3-term):
//   g_gout[M x 256] = (Ah+Al)[M x 256] @ W[256 x 256]
// CTA tile 128x128, 8 warps (4m x 2n), warp tile 32x64, K-step 16.
// 4-stage cp.async ring, one __syncthreads per K-step. Grid (2, 782).
// ---------------------------------------------------------------------------
#define MG_STAGE 24576u
#define MG_SMEM  98304

__global__ void __launch_bounds__(256, 2) k_mgemm(int lidx) {
    extern __shared__ char smem[];
    const uint32_t sb = smem_u32(smem);

    const int tid  = threadIdx.x;
    const int wid  = tid >> 5;
    const int lane = tid & 31;
    const int wm   = wid >> 1;          // 0..3
    const int wn   = wid & 1;           // 0..1
    const int    ncol0 = blockIdx.x * 128;
    const size_t row0  = (size_t)blockIdx.y * 128;

    const __nv_bfloat16* __restrict__ Wh = g_wh + (size_t)lidx * 65536;
    const __nv_bfloat16* __restrict__ Wl = g_wl + (size_t)lidx * 65536;

    const int gr = tid >> 1;            // 0..127 (row / ncol)
    const int gk = (tid & 1) * 8;       // bf16 k offset within 16
    const size_t gA = (row0 + gr) * 256 + gk;
    const size_t gB = ((size_t)(ncol0 + gr)) * 256 + gk;
    const uint32_t sOff = (uint32_t)(gr * 48 + gk * 2);

    const int lr = lane & 7;
    const uint32_t offA = (uint32_t)((wm * 32 + lr + ((lane >> 3) & 1) * 8) * 48
                                     + ((lane >> 4) & 1) * 16);
    const uint32_t offB = (uint32_t)((wn * 64 + lr + ((lane >> 4) & 1) * 8) * 48
                                     + ((lane >> 3) & 1) * 16);

    float acc[2][8][4];
    #pragma unroll
    for (int i = 0; i < 2; i++)
        #pragma unroll
        for (int j = 0; j < 8; j++)
            #pragma unroll
            for (int q = 0; q < 4; q++) acc[i][j][q] = 0.f;

    #pragma unroll
    for (int p = 0; p < 3; p++) {
        const uint32_t bo = (uint32_t)p * MG_STAGE;
        const size_t kk = (size_t)p * 16;
        CP16(sb + bo + sOff,          g_ah + gA + kk);
        CP16(sb + bo + 6144u + sOff,  g_al + gA + kk);
        CP16(sb + bo + 12288u + sOff, Wh + gB + kk);
        CP16(sb + bo + 18432u + sOff, Wl + gB + kk);
        CP_COMMIT();
    }

    for (int c = 0; c < 16; c++) {
        CP_WAIT2();
        __syncthreads();

        if (c + 3 < 16) {
            const uint32_t bo = (uint32_t)((c + 3) & 3) * MG_STAGE;
            const size_t kk = (size_t)(c + 3) * 16;
            CP16(sb + bo + sOff,          g_ah + gA + kk);
            CP16(sb + bo + 6144u + sOff,  g_al + gA + kk);
            CP16(sb + bo + 12288u + sOff, Wh + gB + kk);
            CP16(sb + bo + 18432u + sOff, Wl + gB + kk);
        }
        CP_COMMIT();

        const uint32_t base  = sb + (uint32_t)(c & 3) * MG_STAGE;
        const uint32_t aBase = base + offA;
        const uint32_t bBase = base + 12288u + offB;

        uint32_t ah[2][4], al[2][4], bh[8][2], bl[8][2];
        #pragma unroll
        for (int mi = 0; mi < 2; mi++) {
            LDSM4(ah[mi][0], ah[mi][1], ah[mi][2], ah[mi][3], aBase + mi * 768u);
            LDSM4(al[mi][0], al[mi][1], al[mi][2], al[mi][3], aBase + 6144u + mi * 768u);
        }
        #pragma unroll
        for (int j = 0; j < 4; j++) {
            uint32_t t0, t1, t2, t3;
            LDSM4(t0, t1, t2, t3, bBase + j * 768u);
            bh[2 * j][0] = t0; bh[2 * j][1] = t1;
            bh[2 * j + 1][0] = t2; bh[2 * j + 1][1] = t3;
            LDSM4(t0, t1, t2, t3, bBase + 6144u + j * 768u);
            bl[2 * j][0] = t0; bl[2 * j][1] = t1;
            bl[2 * j + 1][0] = t2; bl[2 * j + 1][1] = t3;
        }

        #pragma unroll
        for (int mi = 0; mi < 2; mi++)
            #pragma unroll
            for (int nj = 0; nj < 8; nj++) {
                MMA16816(acc[mi][nj], ah[mi], bh[nj]);
                MMA16816(acc[mi][nj], ah[mi], bl[nj]);
                MMA16816(acc[mi][nj], al[mi], bh[nj]);
            }
    }

    #pragma unroll
    for (int mi = 0; mi < 2; mi++) {
        const size_t r0 = row0 + wm * 32 + mi * 16 + (lane >> 2);
        const int cc0 = ncol0 + wn * 64 + (lane & 3) * 2;
        #pragma unroll
        for (int nj = 0; nj < 8; nj++) {
            const int cc = cc0 + nj * 8;
            if (r0 < NN)
                *(float2*)&g_gout[r0 * 256 + cc] =
                    make_float2(acc[mi][nj][0], acc[mi][nj][1]);
            if (r0 + 8 < NN)
                *(float2*)&g_gout[(r0 + 8) * 256 + cc] =
                    make_float2(acc[mi][nj][2], acc[mi][nj][3]);
        }
    }
}

// ---------------------------------------------------------------------------
// Shared SpMM gather: returns acc0/acc1 (full 256-f row per warp), with
// self-loop, bias, relu applied. 2x unrolled (r5/r7-verified form).
// ---------------------------------------------------------------------------
__device__ __forceinline__ void spmm_gather(int node, int lane,
                                            const float* __restrict__ bias,
                                            float4& acc0, float4& acc1) {
    const float* __restrict__ H = g_gout;
    int beg = g_rowptr[node];
    int end = g_rowptr[node + 1];

    acc0 = make_float4(0.f, 0.f, 0.f, 0.f);
    acc1 = make_float4(0.f, 0.f, 0.f, 0.f);

    int e = beg;
    for (; e + 1 < end; e += 2) {
        int2 p0 = g_edges[e];
        int2 p1 = g_edges[e + 1];
        float w0 = __int_as_float(p0.y);
        float w1 = __int_as_float(p1.y);
        const float4* hp0 = (const float4*)(H + (size_t)p0.x * 256);
        const float4* hp1 = (const float4*)(H + (size_t)p1.x * 256);
        float4 a0 = hp0[lane];
        float4 b0 = hp0[lane + 32];
        float4 a1 = hp1[lane];
        float4 b1 = hp1[lane + 32];
        acc0.x += w0 * a0.x + w1 * a1.x; acc0.y += w0 * a0.y + w1 * a1.y;
        acc0.z += w0 * a0.z + w1 * a1.z; acc0.w += w0 * a0.w + w1 * a1.w;
        acc1.x += w0 * b0.x + w1 * b1.x; acc1.y += w0 * b0.y + w1 * b1.y;
        acc1.z += w0 * b0.z + w1 * b1.z; acc1.w += w0 * b0.w + w1 * b1.w;
    }
    for (; e < end; e++) {
        int2 p = g_edges[e];
        float w = __int_as_float(p.y);
        const float4* hp = (const float4*)(H + (size_t)p.x * 256);
        float4 a = hp[lane];
        float4 b = hp[lane + 32];
        acc0.x += w * a.x; acc0.y += w * a.y; acc0.z += w * a.z; acc0.w += w * a.w;
        acc1.x += w * b.x; acc1.y += w * b.y; acc1.z += w * b.z; acc1.w += w * b.w;
    }

    float di = g_dinv[node];
    float w2 = di * di;
    {
        const float4* hp = (const float4*)(H + (size_t)node * 256);
        float4 a = hp[lane];
        float4 b = hp[lane + 32];
        acc0.x += w2 * a.x; acc0.y += w2 * a.y; acc0.z += w2 * a.z; acc0.w += w2 * a.w;
        acc1.x += w2 * b.x; acc1.y += w2 * b.y; acc1.z += w2 * b.z; acc1.w += w2 * b.w;
    }

    const float4* bb = (const float4*)bias;
    float4 b0 = bb[lane];
    float4 b1 = bb[lane + 32];
    acc0.x = fmaxf(acc0.x + b0.x, 0.f); acc0.y = fmaxf(acc0.y + b0.y, 0.f);
    acc0.z = fmaxf(acc0.z + b0.z, 0.f); acc0.w = fmaxf(acc0.w + b0.w, 0.f);
    acc1.x = fmaxf(acc1.x + b1.x, 0.f); acc1.y = fmaxf(acc1.y + b1.y, 0.f);
    acc1.z = fmaxf(acc1.z + b1.z, 0.f); acc1.w = fmaxf(acc1.w + b1.w, 0.f);
}

// ---------------------------------------------------------------------------
// SpMM (F=256) for layers 1,2: writes bf16 hi/lo splits for the next GEMM.
// ---------------------------------------------------------------------------
__global__ void __launch_bounds__(256) k_spmm256(const float* __restrict__ bias) {
    int warp = threadIdx.x >> 5;
    int lane = threadIdx.x & 31;
    int node = blockIdx.x * 8 + warp;
    if (node >= NN) return;

    float4 acc0, acc1;
    spmm_gather(node, lane, bias, acc0, acc1);

    size_t base = (size_t)node * 256 + lane * 4;
    split4(acc0, g_ah + base,       g_al + base);
    split4(acc1, g_ah + base + 128, g_al + base + 128);
}

// ---------------------------------------------------------------------------
// Layer-3 SpMM fused with the layer-4 linear: h4 = relu(agg3 + b3) @ W4.
// Each warp holds a full 256-f row; W4 (k-major, padded stride 264) from smem
// via conflict-free LDS.128; 16 partials reduced by warp butterfly.
// Writes g_h4 [NN x 16] (fp32) -- replaces k_gemm16 + 100MB split traffic.
// ---------------------------------------------------------------------------
__global__ void __launch_bounds__(256) k_spmm256_w4(const float* __restrict__ bias,
                                                   const float* __restrict__ W4) {
    __shared__ float Ws[16 * 264];   // Ws[c*264 + k] = W4[k*16 + c]
    for (int idx = threadIdx.x; idx < 4096; idx += 256) {
        int k = idx >> 4, c = idx & 15;
        Ws[c * 264 + k] = W4[idx];
    }
    __syncthreads();

    int warp = threadIdx.x >> 5;
    int lane = threadIdx.x & 31;
    int node = blockIdx.x * 8 + warp;
    if (node >= NN) return;

    float4 acc0, acc1;
    spmm_gather(node, lane, bias, acc0, acc1);

    // row @ W4: lane holds feats [4l..4l+3] (acc0) and [128+4l..128+4l+3] (acc1)
    float p[16];
    #pragma unroll
    for (int c = 0; c < 16; c++) {
        float4 w0 = *(const float4*)&Ws[c * 264 + 4 * lane];
        float4 w1 = *(const float4*)&Ws[c * 264 + 128 + 4 * lane];
        p[c] = acc0.x * w0.x + acc0.y * w0.y + acc0.z * w0.z + acc0.w * w0.w
             + acc1.x * w1.x + acc1.y * w1.y + acc1.z * w1.z + acc1.w * w1.w;
    }
    #pragma unroll
    for (int off = 16; off > 0; off >>= 1)
        #pragma unroll
        for (int c = 0; c < 16; c++)
            p[c] += __shfl_xor_sync(0xffffffffu, p[c], off);

    if (lane < 16)
        g_h4[(size_t)node * 16 + lane] = p[lane];
}

// ---------------------------------------------------------------------------
// SpMM (F=16) + bias + log_softmax -> final output (reads g_h4)
// ---------------------------------------------------------------------------
__global__ void __launch_bounds__(256) k_spmm16(const float* __restrict__ bias,
                                               float* __restrict__ out) {
    const float* __restrict__ H = g_h4;

    int warp = threadIdx.x >> 5;
    int lane = threadIdx.x & 31;
    int node = blockIdx.x * 8 + warp;
    if (node >= NN) return;

    int f = lane & 15;
    int beg = g_rowptr[node];
    int end = g_rowptr[node + 1];

    float acc = 0.f;
    for (int e = beg; e < end; e++) {
        int2 p = g_edges[e];
        acc += __int_as_float(p.y) * H[(size_t)p.x * 16 + f];
    }
    float di = g_dinv[node];
    acc += di * di * H[(size_t)node * 16 + f];
    acc += bias[f];

    float m = acc;
    #pragma unroll
    for (int o = 8; o > 0; o >>= 1)
        m = fmaxf(m, __shfl_xor_sync(0xffffffffu, m, o, 16));
    float ex = expf(acc - m);
    float s = ex;
    #pragma unroll
    for (int o = 8; o > 0; o >>= 1)
        s += __shfl_xor_sync(0xffffffffu, s, o, 16);

    if (lane < 16)
        out[(size_t)node * 16 + f] = (acc - m) - logf(s);
}

// ---------------------------------------------------------------------------
// Launcher — single stream, r5-verified structure + fused layer-4 linear
// ---------------------------------------------------------------------------
extern "C" void kernel_launch(void* const* d_in, const int* in_sizes, int n_in,
                              void* d_out, int out_size)
{
    const float* x  = (const float*)d_in[0];
    const int*   ei = (const int*)  d_in[1];
    const float* W1 = (const float*)d_in[2];
    const float* b1 = (const float*)d_in[3];
    const float* W2 = (const float*)d_in[4];
    const float* b2 = (const float*)d_in[5];
    const float* W3 = (const float*)d_in[6];
    const float* b3 = (const float*)d_in[7];
    const float* W4 = (const float*)d_in[8];
    const float* b4 = (const float*)d_in[9];
    float* out = (float*)d_out;

    static int s_attr_done = 0;
    if (!s_attr_done) {
        cudaFuncSetAttribute(k_mgemm, cudaFuncAttributeMaxDynamicSharedMemorySize, MG_SMEM);
        s_attr_done = 1;
    }

    const int NB_SCAN = (NN + 1023) / 1024;   // 98
    const int sgrid = (NN + 7) / 8;           // 12500

    // graph preprocessing
    k_zero   <<<(NN + 255) / 256, 256>>>();
    k_hist   <<<(EE + 255) / 256, 256>>>(ei);
    k_scan1  <<<NB_SCAN, 1024>>>();
    k_scan2  <<<1, 128>>>();
    k_scan3  <<<NB_SCAN, 1024>>>();
    k_scatter<<<(EE + 255) / 256, 256>>>(ei);

    // operand prep
    k_wsplit <<<768, 256>>>(W1, W2, W3);
    k_xsplit <<<(NN * 64 + 255) / 256, 256>>>(x);

    dim3 ggrid(2, MPAD / 128);                // N-split fastest (L2 reuse of A)

    // layer 1
    k_mgemm  <<<ggrid, 256, MG_SMEM>>>(0);
    k_spmm256<<<sgrid, 256>>>(b1);
    // layer 2
    k_mgemm  <<<ggrid, 256, MG_SMEM>>>(1);
    k_spmm256<<<sgrid, 256>>>(b2);
    // layer 3 (+ fused layer-4 linear)
    k_mgemm  <<<ggrid, 256, MG_SMEM>>>(2);
    k_spmm256_w4<<<sgrid, 256>>>(b3, W4);
    // layer 4 aggregate + log_softmax
    k_spmm16 <<<sgrid, 256>>>(b4, out);
}

// round 10
// speedup vs baseline: 1.3303x; 1.1917x over previous
#include <cuda_runtime.h>
#include <cuda_bf16.h>
#include <cuda_fp16.h>
#include <math.h>
#include <stdint.h>

// Problem constants (fixed by reference)
#define NN   100000
#define EE   1600000
#define MPAD 100096   // 782 * 128

// ---------------------------------------------------------------------------
// Scratch (__device__ globals; no runtime allocation)
// ---------------------------------------------------------------------------
__device__ __half        g_gh[(size_t)MPAD * 256];     // GEMM output (fp16) / SpMM gather input
__device__ __nv_bfloat16 g_ah[(size_t)MPAD * 256];     // activation hi (bf16)
__device__ __nv_bfloat16 g_al[(size_t)MPAD * 256];     // activation lo (bf16)
__device__ __nv_bfloat16 g_wh[3 * 256 * 256];          // W^T hi per layer (n-major, k contig)
__device__ __nv_bfloat16 g_wl[3 * 256 * 256];          // W^T lo per layer
__device__ float         g_h4[(size_t)NN * 16];        // fused layer-4 pre-agg (fp32)
__device__ int   g_deg[NN];
__device__ float g_dinv[NN];
__device__ int   g_rowptr[NN + 1];
__device__ int   g_cursor[NN];
__device__ int   g_bsum[128];
__device__ int2  g_edges[EE];                          // packed (src, norm-bits)

// ---------------------------------------------------------------------------
// PTX helpers (sm_80-era; valid on plain compute_100 target)
// ---------------------------------------------------------------------------
__device__ __forceinline__ uint32_t smem_u32(const void* p) {
    uint32_t a;
    asm("{ .reg .u64 t; cvta.to.shared.u64 t, %1; cvt.u32.u64 %0, t; }"
        : "=r"(a) : "l"(p));
    return a;
}

#define CP16(smem_addr, gptr) \
    asm volatile("cp.async.cg.shared.global [%0], [%1], 16;" \
        :: "r"(smem_addr), "l"(gptr) : "memory")
#define CP_COMMIT() asm volatile("cp.async.commit_group;" ::: "memory")
#define CP_WAIT2()  asm volatile("cp.async.wait_group 2;" ::: "memory")

#define LDSM4(r0, r1, r2, r3, addr) \
    asm volatile("ldmatrix.sync.aligned.m8n8.x4.shared.b16 {%0,%1,%2,%3}, [%4];" \
        : "=r"(r0), "=r"(r1), "=r"(r2), "=r"(r3) : "r"(addr))

#define MMA16816(d, a, b) \
    asm volatile("mma.sync.aligned.m16n8k16.row.col.f32.bf16.bf16.f32 " \
        "{%0,%1,%2,%3},{%4,%5,%6,%7},{%8,%9},{%0,%1,%2,%3};" \
        : "+f"((d)[0]), "+f"((d)[1]), "+f"((d)[2]), "+f"((d)[3]) \
        : "r"((a)[0]), "r"((a)[1]), "r"((a)[2]), "r"((a)[3]), \
          "r"((b)[0]), "r"((b)[1]))

// ---------------------------------------------------------------------------
// bf16 hi/lo split helper
// ---------------------------------------------------------------------------
__device__ __forceinline__ void split4(float4 v, __nv_bfloat16* ph, __nv_bfloat16* pl) {
    __nv_bfloat162 h0 = __floats2bfloat162_rn(v.x, v.y);
    __nv_bfloat162 h1 = __floats2bfloat162_rn(v.z, v.w);
    float2 f0 = __bfloat1622float2(h0);
    float2 f1 = __bfloat1622float2(h1);
    __nv_bfloat162 l0 = __floats2bfloat162_rn(v.x - f0.x, v.y - f0.y);
    __nv_bfloat162 l1 = __floats2bfloat162_rn(v.z - f1.x, v.w - f1.y);
    *(__nv_bfloat162*)(ph)     = h0;
    *(__nv_bfloat162*)(ph + 2) = h1;
    *(__nv_bfloat162*)(pl)     = l0;
    *(__nv_bfloat162*)(pl + 2) = l1;
}

// ---------------------------------------------------------------------------
// k_prep: fused zero(g_deg) + wsplit + xsplit (independent jobs)
// blocks [0,391): zero; [391,1159): wsplit; [1159,26159): xsplit
// ---------------------------------------------------------------------------
__global__ void __launch_bounds__(256) k_prep(const float* __restrict__ x,
                                             const float* __restrict__ W1,
                                             const float* __restrict__ W2,
                                             const float* __restrict__ W3) {
    int bid = blockIdx.x;
    if (bid < 391) {
        int i = bid * 256 + threadIdx.x;
        if (i < NN) g_deg[i] = 0;
    } else if (bid < 1159) {
        int idx = (bid - 391) * 256 + threadIdx.x;   // 0..196607
        int l = idx >> 16;
        int r = idx & 65535;
        int k = r >> 8, n = r & 255;
        const float* W = (l == 0) ? W1 : ((l == 1) ? W2 : W3);
        float v = W[k * 256 + n];
        __nv_bfloat16 hi = __float2bfloat16(v);
        g_wh[l * 65536 + n * 256 + k] = hi;
        g_wl[l * 65536 + n * 256 + k] = __float2bfloat16(v - __bfloat162float(hi));
    } else {
        size_t i = (size_t)(bid - 1159) * 256 + threadIdx.x;   // float4 index
        if (i < (size_t)NN * 64) {
            float4 v = ((const float4*)x)[i];
            split4(v, g_ah + i * 4, g_al + i * 4);
        }
    }
}

// ---------------------------------------------------------------------------
// Graph preprocessing
// ---------------------------------------------------------------------------
__global__ void k_hist(const int* __restrict__ ei) {
    int e = blockIdx.x * blockDim.x + threadIdx.x;
    if (e < EE) atomicAdd(&g_deg[ei[EE + e]], 1);
}

__global__ void k_scan1() {
    __shared__ int sh[1024];
    int i = blockIdx.x * 1024 + threadIdx.x;
    int v = (i < NN) ? g_deg[i] : 0;
    if (i < NN) g_dinv[i] = rsqrtf((float)v + 1.0f);
    sh[threadIdx.x] = v;
    __syncthreads();
    #pragma unroll
    for (int off = 1; off < 1024; off <<= 1) {
        int t = (threadIdx.x >= off) ? sh[threadIdx.x - off] : 0;
        __syncthreads();
        sh[threadIdx.x] += t;
        __syncthreads();
    }
    if (i < NN) g_rowptr[i] = sh[threadIdx.x] - v;
    if (threadIdx.x == 1023) g_bsum[blockIdx.x] = sh[1023];
}

__global__ void k_scan2() {
    __shared__ int sh[128];
    const int NB = (NN + 1023) / 1024;
    int v = (threadIdx.x < NB) ? g_bsum[threadIdx.x] : 0;
    sh[threadIdx.x] = v;
    __syncthreads();
    #pragma unroll
    for (int off = 1; off < 128; off <<= 1) {
        int t = (threadIdx.x >= off) ? sh[threadIdx.x - off] : 0;
        __syncthreads();
        sh[threadIdx.x] += t;
        __syncthreads();
    }
    g_bsum[threadIdx.x] = sh[threadIdx.x] - v;
}

__global__ void k_scan3() {
    int i = blockIdx.x * 1024 + threadIdx.x;
    if (i < NN) {
        g_rowptr[i] += g_bsum[blockIdx.x];
        g_cursor[i] = 0;
    }
    if (i == 0) g_rowptr[NN] = EE;
}

__global__ void k_scatter(const int* __restrict__ ei) {
    int e = blockIdx.x * blockDim.x + threadIdx.x;
    if (e >= EE) return;
    int s = ei[e];
    int d = ei[EE + e];
    int pos = g_rowptr[d] + atomicAdd(&g_cursor[d], 1);
    g_edges[pos] = make_int2(s, __float_as_int(g_dinv[s] * g_dinv[d]));
}

// ---------------------------------------------------------------------------
// Tensor GEMM via mma.sync (bf16 split 3-term):
//   g_gh[M x 256] (fp16) = (Ah+Al)[M x 256] @ W[256 x 256]
// CTA tile 128x128, 8 warps (4m x 2n), warp tile 32x64, K-step 16.
// 4-stage cp.async ring, one __syncthreads per K-step. Grid (2, 782).
// ---------------------------------------------------------------------------
#define MG_STAGE 24576u
#define MG_SMEM  98304

__global__ void __launch_bounds__(256, 2) k_mgemm(int lidx) {
    extern __shared__ char smem[];
    const uint32_t sb = smem_u32(smem);

    const int tid  = threadIdx.x;
    const int wid  = tid >> 5;
    const int lane = tid & 31;
    const int wm   = wid >> 1;          // 0..3
    const int wn   = wid & 1;           // 0..1
    const int    ncol0 = blockIdx.x * 128;
    const size_t row0  = (size_t)blockIdx.y * 128;

    const __nv_bfloat16* __restrict__ Wh = g_wh + (size_t)lidx * 65536;
    const __nv_bfloat16* __restrict__ Wl = g_wl + (size_t)lidx * 65536;

    const int gr = tid >> 1;            // 0..127 (row / ncol)
    const int gk = (tid & 1) * 8;       // bf16 k offset within 16
    const size_t gA = (row0 + gr) * 256 + gk;
    const size_t gB = ((size_t)(ncol0 + gr)) * 256 + gk;
    const uint32_t sOff = (uint32_t)(gr * 48 + gk * 2);

    const int lr = lane & 7;
    const uint32_t offA = (uint32_t)((wm * 32 + lr + ((lane >> 3) & 1) * 8) * 48
                                     + ((lane >> 4) & 1) * 16);
    const uint32_t offB = (uint32_t)((wn * 64 + lr + ((lane >> 4) & 1) * 8) * 48
                                     + ((lane >> 3) & 1) * 16);

    float acc[2][8][4];
    #pragma unroll
    for (int i = 0; i < 2; i++)
        #pragma unroll
        for (int j = 0; j < 8; j++)
            #pragma unroll
            for (int q = 0; q < 4; q++) acc[i][j][q] = 0.f;

    #pragma unroll
    for (int p = 0; p < 3; p++) {
        const uint32_t bo = (uint32_t)p * MG_STAGE;
        const size_t kk = (size_t)p * 16;
        CP16(sb + bo + sOff,          g_ah + gA + kk);
        CP16(sb + bo + 6144u + sOff,  g_al + gA + kk);
        CP16(sb + bo + 12288u + sOff, Wh + gB + kk);
        CP16(sb + bo + 18432u + sOff, Wl + gB + kk);
        CP_COMMIT();
    }

    for (int c = 0; c < 16; c++) {
        CP_WAIT2();
        __syncthreads();

        if (c + 3 < 16) {
            const uint32_t bo = (uint32_t)((c + 3) & 3) * MG_STAGE;
            const size_t kk = (size_t)(c + 3) * 16;
            CP16(sb + bo + sOff,          g_ah + gA + kk);
            CP16(sb + bo + 6144u + sOff,  g_al + gA + kk);
            CP16(sb + bo + 12288u + sOff, Wh + gB + kk);
            CP16(sb + bo + 18432u + sOff, Wl + gB + kk);
        }
        CP_COMMIT();

        const uint32_t base  = sb + (uint32_t)(c & 3) * MG_STAGE;
        const uint32_t aBase = base + offA;
        const uint32_t bBase = base + 12288u + offB;

        uint32_t ah[2][4], al[2][4], bh[8][2], bl[8][2];
        #pragma unroll
        for (int mi = 0; mi < 2; mi++) {
            LDSM4(ah[mi][0], ah[mi][1], ah[mi][2], ah[mi][3], aBase + mi * 768u);
            LDSM4(al[mi][0], al[mi][1], al[mi][2], al[mi][3], aBase + 6144u + mi * 768u);
        }
        #pragma unroll
        for (int j = 0; j < 4; j++) {
            uint32_t t0, t1, t2, t3;
            LDSM4(t0, t1, t2, t3, bBase + j * 768u);
            bh[2 * j][0] = t0; bh[2 * j][1] = t1;
            bh[2 * j + 1][0] = t2; bh[2 * j + 1][1] = t3;
            LDSM4(t0, t1, t2, t3, bBase + 6144u + j * 768u);
            bl[2 * j][0] = t0; bl[2 * j][1] = t1;
            bl[2 * j + 1][0] = t2; bl[2 * j + 1][1] = t3;
        }

        #pragma unroll
        for (int mi = 0; mi < 2; mi++)
            #pragma unroll
            for (int nj = 0; nj < 8; nj++) {
                MMA16816(acc[mi][nj], ah[mi], bh[nj]);
                MMA16816(acc[mi][nj], ah[mi], bl[nj]);
                MMA16816(acc[mi][nj], al[mi], bh[nj]);
            }
    }

    // epilogue: write fp16
    #pragma unroll
    for (int mi = 0; mi < 2; mi++) {
        const size_t r0 = row0 + wm * 32 + mi * 16 + (lane >> 2);
        const int cc0 = ncol0 + wn * 64 + (lane & 3) * 2;
        #pragma unroll
        for (int nj = 0; nj < 8; nj++) {
            const int cc = cc0 + nj * 8;
            if (r0 < NN)
                *(__half2*)&g_gh[r0 * 256 + cc] =
                    __floats2half2_rn(acc[mi][nj][0], acc[mi][nj][1]);
            if (r0 + 8 < NN)
                *(__half2*)&g_gh[(r0 + 8) * 256 + cc] =
                    __floats2half2_rn(acc[mi][nj][2], acc[mi][nj][3]);
        }
    }
}

// ---------------------------------------------------------------------------
// Shared SpMM gather over fp16 rows: lane covers feats [8l..8l+7] via one
// uint4 (16 B) per edge row. Self-loop + bias + relu applied.
// ---------------------------------------------------------------------------
__device__ __forceinline__ void acc8(float* acc, uint4 v, float w) {
    float2 f0 = __half22float2(*(__half2*)&v.x);
    float2 f1 = __half22float2(*(__half2*)&v.y);
    float2 f2 = __half22float2(*(__half2*)&v.z);
    float2 f3 = __half22float2(*(__half2*)&v.w);
    acc[0] += w * f0.x; acc[1] += w * f0.y;
    acc[2] += w * f1.x; acc[3] += w * f1.y;
    acc[4] += w * f2.x; acc[5] += w * f2.y;
    acc[6] += w * f3.x; acc[7] += w * f3.y;
}

__device__ __forceinline__ void spmm_gather(int node, int lane,
                                            const float* __restrict__ bias,
                                            float* acc) {
    const __half* __restrict__ H = g_gh;
    int beg = g_rowptr[node];
    int end = g_rowptr[node + 1];

    #pragma unroll
    for (int i = 0; i < 8; i++) acc[i] = 0.f;

    int e = beg;
    for (; e + 1 < end; e += 2) {
        int2 p0 = g_edges[e];
        int2 p1 = g_edges[e + 1];
        float w0 = __int_as_float(p0.y);
        float w1 = __int_as_float(p1.y);
        uint4 v0 = *((const uint4*)(H + (size_t)p0.x * 256) + lane);
        uint4 v1 = *((const uint4*)(H + (size_t)p1.x * 256) + lane);
        acc8(acc, v0, w0);
        acc8(acc, v1, w1);
    }
    for (; e < end; e++) {
        int2 p = g_edges[e];
        float w = __int_as_float(p.y);
        uint4 v = *((const uint4*)(H + (size_t)p.x * 256) + lane);
        acc8(acc, v, w);
    }

    // self-loop
    float di = g_dinv[node];
    {
        uint4 v = *((const uint4*)(H + (size_t)node * 256) + lane);
        acc8(acc, v, di * di);
    }

    // bias + relu (lane covers feats 8l..8l+7)
    const float4* bb = (const float4*)bias;
    float4 b0 = bb[2 * lane];
    float4 b1 = bb[2 * lane + 1];
    acc[0] = fmaxf(acc[0] + b0.x, 0.f); acc[1] = fmaxf(acc[1] + b0.y, 0.f);
    acc[2] = fmaxf(acc[2] + b0.z, 0.f); acc[3] = fmaxf(acc[3] + b0.w, 0.f);
    acc[4] = fmaxf(acc[4] + b1.x, 0.f); acc[5] = fmaxf(acc[5] + b1.y, 0.f);
    acc[6] = fmaxf(acc[6] + b1.z, 0.f); acc[7] = fmaxf(acc[7] + b1.w, 0.f);
}

// ---------------------------------------------------------------------------
// SpMM (F=256) for layers 1,2: writes bf16 hi/lo splits for the next GEMM.
// ---------------------------------------------------------------------------
__global__ void __launch_bounds__(256) k_spmm256(const float* __restrict__ bias) {
    int warp = threadIdx.x >> 5;
    int lane = threadIdx.x & 31;
    int node = blockIdx.x * 8 + warp;
    if (node >= NN) return;

    float acc[8];
    spmm_gather(node, lane, bias, acc);

    float4 a0 = make_float4(acc[0], acc[1], acc[2], acc[3]);
    float4 a1 = make_float4(acc[4], acc[5], acc[6], acc[7]);
    size_t base = (size_t)node * 256 + lane * 8;
    split4(a0, g_ah + base,     g_al + base);
    split4(a1, g_ah + base + 4, g_al + base + 4);
}

// ---------------------------------------------------------------------------
// Layer-3 SpMM fused with the layer-4 linear: h4 = relu(agg3 + b3) @ W4.
// Lane holds feats [8l..8l+7]; W4 k-major in smem (stride 264); butterfly.
// ---------------------------------------------------------------------------
__global__ void __launch_bounds__(256) k_spmm256_w4(const float* __restrict__ bias,
                                                   const float* __restrict__ W4) {
    __shared__ float Ws[16 * 264];   // Ws[c*264 + k] = W4[k*16 + c]
    for (int idx = threadIdx.x; idx < 4096; idx += 256) {
        int k = idx >> 4, c = idx & 15;
        Ws[c * 264 + k] = W4[idx];
    }
    __syncthreads();

    int warp = threadIdx.x >> 5;
    int lane = threadIdx.x & 31;
    int node = blockIdx.x * 8 + warp;
    if (node >= NN) return;

    float acc[8];
    spmm_gather(node, lane, bias, acc);

    float p[16];
    #pragma unroll
    for (int c = 0; c < 16; c++) {
        float4 w0 = *(const float4*)&Ws[c * 264 + 8 * lane];
        float4 w1 = *(const float4*)&Ws[c * 264 + 8 * lane + 4];
        p[c] = acc[0] * w0.x + acc[1] * w0.y + acc[2] * w0.z + acc[3] * w0.w
             + acc[4] * w1.x + acc[5] * w1.y + acc[6] * w1.z + acc[7] * w1.w;
    }
    #pragma unroll
    for (int off = 16; off > 0; off >>= 1)
        #pragma unroll
        for (int c = 0; c < 16; c++)
            p[c] += __shfl_xor_sync(0xffffffffu, p[c], off);

    if (lane < 16)
        g_h4[(size_t)node * 16 + lane] = p[lane];
}

// ---------------------------------------------------------------------------
// SpMM (F=16) + bias + log_softmax -> final output (reads g_h4, fp32)
// ---------------------------------------------------------------------------
__global__ void __launch_bounds__(256) k_spmm16(const float* __restrict__ bias,
                                               float* __restrict__ out) {
    const float* __restrict__ H = g_h4;

    int warp = threadIdx.x >> 5;
    int lane = threadIdx.x & 31;
    int node = blockIdx.x * 8 + warp;
    if (node >= NN) return;

    int f = lane & 15;
    int beg = g_rowptr[node];
    int end = g_rowptr[node + 1];

    float acc = 0.f;
    for (int e = beg; e < end; e++) {
        int2 p = g_edges[e];
        acc += __int_as_float(p.y) * H[(size_t)p.x * 16 + f];
    }
    float di = g_dinv[node];
    acc += di * di * H[(size_t)node * 16 + f];
    acc += bias[f];

    float m = acc;
    #pragma unroll
    for (int o = 8; o > 0; o >>= 1)
        m = fmaxf(m, __shfl_xor_sync(0xffffffffu, m, o, 16));
    float ex = expf(acc - m);
    float s = ex;
    #pragma unroll
    for (int o = 8; o > 0; o >>= 1)
        s += __shfl_xor_sync(0xffffffffu, s, o, 16);

    if (lane < 16)
        out[(size_t)node * 16 + f] = (acc - m) - logf(s);
}

// ---------------------------------------------------------------------------
// Launcher — single stream
// ---------------------------------------------------------------------------
extern "C" void kernel_launch(void* const* d_in, const int* in_sizes, int n_in,
                              void* d_out, int out_size)
{
    const float* x  = (const float*)d_in[0];
    const int*   ei = (const int*)  d_in[1];
    const float* W1 = (const float*)d_in[2];
    const float* b1 = (const float*)d_in[3];
    const float* W2 = (const float*)d_in[4];
    const float* b2 = (const float*)d_in[5];
    const float* W3 = (const float*)d_in[6];
    const float* b3 = (const float*)d_in[7];
    const float* W4 = (const float*)d_in[8];
    const float* b4 = (const float*)d_in[9];
    float* out = (float*)d_out;

    static int s_attr_done = 0;
    if (!s_attr_done) {
        cudaFuncSetAttribute(k_mgemm, cudaFuncAttributeMaxDynamicSharedMemorySize, MG_SMEM);
        s_attr_done = 1;
    }

    const int NB_SCAN = (NN + 1023) / 1024;   // 98
    const int sgrid = (NN + 7) / 8;           // 12500

    // prep: zero(g_deg) + weight split + x split (independent, one kernel)
    k_prep   <<<26159, 256>>>(x, W1, W2, W3);

    // graph preprocessing
    k_hist   <<<(EE + 255) / 256, 256>>>(ei);
    k_scan1  <<<NB_SCAN, 1024>>>();
    k_scan2  <<<1, 128>>>();
    k_scan3  <<<NB_SCAN, 1024>>>();
    k_scatter<<<(EE + 255) / 256, 256>>>(ei);

    dim3 ggrid(2, MPAD / 128);                // N-split fastest (L2 reuse of A)

    // layer 1
    k_mgemm  <<<ggrid, 256, MG_SMEM>>>(0);
    k_spmm256<<<sgrid, 256>>>(b1);
    // layer 2
    k_mgemm  <<<ggrid, 256, MG_SMEM>>>(1);
    k_spmm256<<<sgrid, 256>>>(b2);
    // layer 3 (+ fused layer-4 linear)
    k_mgemm  <<<ggrid, 256, MG_SMEM>>>(2);
    k_spmm256_w4<<<sgrid, 256>>>(b3, W4);
    // layer 4 aggregate + log_softmax
    k_spmm16 <<<sgrid, 256>>>(b4, out);
}

// round 11
// speedup vs baseline: 1.8277x; 1.3740x over previous
#include <cuda_runtime.h>
#include <cuda_bf16.h>
#include <cuda_fp16.h>
#include <math.h>
#include <stdint.h>

// Problem constants (fixed by reference)
#define NN   100000
#define EE   1600000
#define MPAD 100096   // 782 * 128

// ---------------------------------------------------------------------------
// Scratch (__device__ globals; no runtime allocation)
// ---------------------------------------------------------------------------
__device__ __half g_gh[(size_t)MPAD * 256];    // GEMM output (fp16) / SpMM gather input
__device__ __half g_act[(size_t)MPAD * 256];   // activations (fp16) / GEMM A input
__device__ __half g_wf[3 * 256 * 256];         // W^T per layer (n-major, k contig, fp16)
__device__ float  g_h4[(size_t)NN * 16];       // fused layer-4 pre-agg (fp32)
__device__ int    g_deg[NN];
__device__ float  g_dinv[NN];
__device__ int    g_rowptr[NN + 1];
__device__ int    g_cursor[NN];
__device__ int    g_bsum[128];
__device__ int2   g_edges[EE];                 // packed (src, norm-bits)

// ---------------------------------------------------------------------------
// PTX helpers (sm_80-era; valid on plain compute_100 target)
// ---------------------------------------------------------------------------
__device__ __forceinline__ uint32_t smem_u32(const void* p) {
    uint32_t a;
    asm("{ .reg .u64 t; cvta.to.shared.u64 t, %1; cvt.u32.u64 %0, t; }"
        : "=r"(a) : "l"(p));
    return a;
}

#define CP16(smem_addr, gptr) \
    asm volatile("cp.async.cg.shared.global [%0], [%1], 16;" \
        :: "r"(smem_addr), "l"(gptr) : "memory")
#define CP_COMMIT() asm volatile("cp.async.commit_group;" ::: "memory")
#define CP_WAIT2()  asm volatile("cp.async.wait_group 2;" ::: "memory")

#define LDSM4(r0, r1, r2, r3, addr) \
    asm volatile("ldmatrix.sync.aligned.m8n8.x4.shared.b16 {%0,%1,%2,%3}, [%4];" \
        : "=r"(r0), "=r"(r1), "=r"(r2), "=r"(r3) : "r"(addr))

#define MMA16816H(d, a, b) \
    asm volatile("mma.sync.aligned.m16n8k16.row.col.f32.f16.f16.f32 " \
        "{%0,%1,%2,%3},{%4,%5,%6,%7},{%8,%9},{%0,%1,%2,%3};" \
        : "+f"((d)[0]), "+f"((d)[1]), "+f"((d)[2]), "+f"((d)[3]) \
        : "r"((a)[0]), "r"((a)[1]), "r"((a)[2]), "r"((a)[3]), \
          "r"((b)[0]), "r"((b)[1]))

// ---------------------------------------------------------------------------
// k_prep: fused zero(g_deg) + W->fp16 transpose + x->fp16 convert
// blocks [0,391): zero; [391,1159): wconv; [1159,26159): xconv
// ---------------------------------------------------------------------------
__global__ void __launch_bounds__(256) k_prep(const float* __restrict__ x,
                                             const float* __restrict__ W1,
                                             const float* __restrict__ W2,
                                             const float* __restrict__ W3) {
    int bid = blockIdx.x;
    if (bid < 391) {
        int i = bid * 256 + threadIdx.x;
        if (i < NN) g_deg[i] = 0;
    } else if (bid < 1159) {
        int idx = (bid - 391) * 256 + threadIdx.x;   // 0..196607
        int l = idx >> 16;
        int r = idx & 65535;
        int k = r >> 8, n = r & 255;
        const float* W = (l == 0) ? W1 : ((l == 1) ? W2 : W3);
        g_wf[l * 65536 + n * 256 + k] = __float2half_rn(W[k * 256 + n]);
    } else {
        size_t i = (size_t)(bid - 1159) * 256 + threadIdx.x;   // float4 index
        if (i < (size_t)NN * 64) {
            float4 v = ((const float4*)x)[i];
            uint2 h;
            *(__half2*)&h.x = __floats2half2_rn(v.x, v.y);
            *(__half2*)&h.y = __floats2half2_rn(v.z, v.w);
            *(uint2*)(g_act + i * 4) = h;
        }
    }
}

// ---------------------------------------------------------------------------
// Graph preprocessing
// ---------------------------------------------------------------------------
__global__ void k_hist(const int* __restrict__ ei) {
    int e = blockIdx.x * blockDim.x + threadIdx.x;
    if (e < EE) atomicAdd(&g_deg[ei[EE + e]], 1);
}

__global__ void k_scan1() {
    __shared__ int sh[1024];
    int i = blockIdx.x * 1024 + threadIdx.x;
    int v = (i < NN) ? g_deg[i] : 0;
    if (i < NN) g_dinv[i] = rsqrtf((float)v + 1.0f);
    sh[threadIdx.x] = v;
    __syncthreads();
    #pragma unroll
    for (int off = 1; off < 1024; off <<= 1) {
        int t = (threadIdx.x >= off) ? sh[threadIdx.x - off] : 0;
        __syncthreads();
        sh[threadIdx.x] += t;
        __syncthreads();
    }
    if (i < NN) g_rowptr[i] = sh[threadIdx.x] - v;
    if (threadIdx.x == 1023) g_bsum[blockIdx.x] = sh[1023];
}

__global__ void k_scan2() {
    __shared__ int sh[128];
    const int NB = (NN + 1023) / 1024;
    int v = (threadIdx.x < NB) ? g_bsum[threadIdx.x] : 0;
    sh[threadIdx.x] = v;
    __syncthreads();
    #pragma unroll
    for (int off = 1; off < 128; off <<= 1) {
        int t = (threadIdx.x >= off) ? sh[threadIdx.x - off] : 0;
        __syncthreads();
        sh[threadIdx.x] += t;
        __syncthreads();
    }
    g_bsum[threadIdx.x] = sh[threadIdx.x] - v;
}

__global__ void k_scan3() {
    int i = blockIdx.x * 1024 + threadIdx.x;
    if (i < NN) {
        g_rowptr[i] += g_bsum[blockIdx.x];
        g_cursor[i] = 0;
    }
    if (i == 0) g_rowptr[NN] = EE;
}

__global__ void k_scatter(const int* __restrict__ ei) {
    int e = blockIdx.x * blockDim.x + threadIdx.x;
    if (e >= EE) return;
    int s = ei[e];
    int d = ei[EE + e];
    int pos = g_rowptr[d] + atomicAdd(&g_cursor[d], 1);
    g_edges[pos] = make_int2(s, __float_as_int(g_dinv[s] * g_dinv[d]));
}

// ---------------------------------------------------------------------------
// fp16 tensor GEMM via mma.sync:
//   g_gh[M x 256] (fp16) = g_act[M x 256] (fp16) @ W[256 x 256] (fp16)
// CTA tile 128x128, 8 warps (4m x 2n), warp tile 32x64, K-step 16.
// 4-stage cp.async ring (stage = A 6144 B + B 6144 B), one barrier/K-step.
// Grid (2, 782): N-split fastest so sibling CTAs share A tiles in L2.
// ---------------------------------------------------------------------------
#define MG_STAGE 12288u
#define MG_SMEM  49152

__global__ void __launch_bounds__(256, 2) k_mgemm(int lidx) {
    extern __shared__ char smem[];
    const uint32_t sb = smem_u32(smem);

    const int tid  = threadIdx.x;
    const int wid  = tid >> 5;
    const int lane = tid & 31;
    const int wm   = wid >> 1;          // 0..3
    const int wn   = wid & 1;           // 0..1
    const int    ncol0 = blockIdx.x * 128;
    const size_t row0  = (size_t)blockIdx.y * 128;

    const __half* __restrict__ Wf = g_wf + (size_t)lidx * 65536;

    const int gr = tid >> 1;            // 0..127 (row / ncol)
    const int gk = (tid & 1) * 8;       // fp16 k offset within 16
    const size_t gA = (row0 + gr) * 256 + gk;
    const size_t gB = ((size_t)(ncol0 + gr)) * 256 + gk;
    const uint32_t sOff = (uint32_t)(gr * 48 + gk * 2);

    const int lr = lane & 7;
    const uint32_t offA = (uint32_t)((wm * 32 + lr + ((lane >> 3) & 1) * 8) * 48
                                     + ((lane >> 4) & 1) * 16);
    const uint32_t offB = (uint32_t)((wn * 64 + lr + ((lane >> 4) & 1) * 8) * 48
                                     + ((lane >> 3) & 1) * 16);

    float acc[2][8][4];
    #pragma unroll
    for (int i = 0; i < 2; i++)
        #pragma unroll
        for (int j = 0; j < 8; j++)
            #pragma unroll
            for (int q = 0; q < 4; q++) acc[i][j][q] = 0.f;

    #pragma unroll
    for (int p = 0; p < 3; p++) {
        const uint32_t bo = (uint32_t)p * MG_STAGE;
        const size_t kk = (size_t)p * 16;
        CP16(sb + bo + sOff,         g_act + gA + kk);
        CP16(sb + bo + 6144u + sOff, Wf + gB + kk);
        CP_COMMIT();
    }

    for (int c = 0; c < 16; c++) {
        CP_WAIT2();
        __syncthreads();

        if (c + 3 < 16) {
            const uint32_t bo = (uint32_t)((c + 3) & 3) * MG_STAGE;
            const size_t kk = (size_t)(c + 3) * 16;
            CP16(sb + bo + sOff,         g_act + gA + kk);
            CP16(sb + bo + 6144u + sOff, Wf + gB + kk);
        }
        CP_COMMIT();

        const uint32_t base  = sb + (uint32_t)(c & 3) * MG_STAGE;
        const uint32_t aBase = base + offA;
        const uint32_t bBase = base + 6144u + offB;

        uint32_t ah[2][4], bh[8][2];
        #pragma unroll
        for (int mi = 0; mi < 2; mi++)
            LDSM4(ah[mi][0], ah[mi][1], ah[mi][2], ah[mi][3], aBase + mi * 768u);
        #pragma unroll
        for (int j = 0; j < 4; j++) {
            uint32_t t0, t1, t2, t3;
            LDSM4(t0, t1, t2, t3, bBase + j * 768u);
            bh[2 * j][0] = t0; bh[2 * j][1] = t1;
            bh[2 * j + 1][0] = t2; bh[2 * j + 1][1] = t3;
        }

        #pragma unroll
        for (int mi = 0; mi < 2; mi++)
            #pragma unroll
            for (int nj = 0; nj < 8; nj++)
                MMA16816H(acc[mi][nj], ah[mi], bh[nj]);
    }

    // epilogue: write fp16
    #pragma unroll
    for (int mi = 0; mi < 2; mi++) {
        const size_t r0 = row0 + wm * 32 + mi * 16 + (lane >> 2);
        const int cc0 = ncol0 + wn * 64 + (lane & 3) * 2;
        #pragma unroll
        for (int nj = 0; nj < 8; nj++) {
            const int cc = cc0 + nj * 8;
            if (r0 < NN)
                *(__half2*)&g_gh[r0 * 256 + cc] =
                    __floats2half2_rn(acc[mi][nj][0], acc[mi][nj][1]);
            if (r0 + 8 < NN)
                *(__half2*)&g_gh[(r0 + 8) * 256 + cc] =
                    __floats2half2_rn(acc[mi][nj][2], acc[mi][nj][3]);
        }
    }
}

// ---------------------------------------------------------------------------
// Shared SpMM gather over fp16 rows: lane covers feats [8l..8l+7] via one
// uint4 (16 B) per edge row. Self-loop + bias + relu applied.
// ---------------------------------------------------------------------------
__device__ __forceinline__ void acc8(float* acc, uint4 v, float w) {
    float2 f0 = __half22float2(*(__half2*)&v.x);
    float2 f1 = __half22float2(*(__half2*)&v.y);
    float2 f2 = __half22float2(*(__half2*)&v.z);
    float2 f3 = __half22float2(*(__half2*)&v.w);
    acc[0] += w * f0.x; acc[1] += w * f0.y;
    acc[2] += w * f1.x; acc[3] += w * f1.y;
    acc[4] += w * f2.x; acc[5] += w * f2.y;
    acc[6] += w * f3.x; acc[7] += w * f3.y;
}

__device__ __forceinline__ void spmm_gather(int node, int lane,
                                            const float* __restrict__ bias,
                                            float* acc) {
    const __half* __restrict__ H = g_gh;
    int beg = g_rowptr[node];
    int end = g_rowptr[node + 1];

    #pragma unroll
    for (int i = 0; i < 8; i++) acc[i] = 0.f;

    int e = beg;
    for (; e + 1 < end; e += 2) {
        int2 p0 = g_edges[e];
        int2 p1 = g_edges[e + 1];
        float w0 = __int_as_float(p0.y);
        float w1 = __int_as_float(p1.y);
        uint4 v0 = *((const uint4*)(H + (size_t)p0.x * 256) + lane);
        uint4 v1 = *((const uint4*)(H + (size_t)p1.x * 256) + lane);
        acc8(acc, v0, w0);
        acc8(acc, v1, w1);
    }
    for (; e < end; e++) {
        int2 p = g_edges[e];
        float w = __int_as_float(p.y);
        uint4 v = *((const uint4*)(H + (size_t)p.x * 256) + lane);
        acc8(acc, v, w);
    }

    // self-loop
    float di = g_dinv[node];
    {
        uint4 v = *((const uint4*)(H + (size_t)node * 256) + lane);
        acc8(acc, v, di * di);
    }

    // bias + relu (lane covers feats 8l..8l+7)
    const float4* bb = (const float4*)bias;
    float4 b0 = bb[2 * lane];
    float4 b1 = bb[2 * lane + 1];
    acc[0] = fmaxf(acc[0] + b0.x, 0.f); acc[1] = fmaxf(acc[1] + b0.y, 0.f);
    acc[2] = fmaxf(acc[2] + b0.z, 0.f); acc[3] = fmaxf(acc[3] + b0.w, 0.f);
    acc[4] = fmaxf(acc[4] + b1.x, 0.f); acc[5] = fmaxf(acc[5] + b1.y, 0.f);
    acc[6] = fmaxf(acc[6] + b1.z, 0.f); acc[7] = fmaxf(acc[7] + b1.w, 0.f);
}

// ---------------------------------------------------------------------------
// SpMM (F=256) for layers 1,2: writes fp16 activations for the next GEMM.
// ---------------------------------------------------------------------------
__global__ void __launch_bounds__(256) k_spmm256(const float* __restrict__ bias) {
    int warp = threadIdx.x >> 5;
    int lane = threadIdx.x & 31;
    int node = blockIdx.x * 8 + warp;
    if (node >= NN) return;

    float acc[8];
    spmm_gather(node, lane, bias, acc);

    uint4 h;
    *(__half2*)&h.x = __floats2half2_rn(acc[0], acc[1]);
    *(__half2*)&h.y = __floats2half2_rn(acc[2], acc[3]);
    *(__half2*)&h.z = __floats2half2_rn(acc[4], acc[5]);
    *(__half2*)&h.w = __floats2half2_rn(acc[6], acc[7]);
    *((uint4*)(g_act + (size_t)node * 256) + lane) = h;
}

// ---------------------------------------------------------------------------
// Layer-3 SpMM fused with the layer-4 linear: h4 = relu(agg3 + b3) @ W4.
// Lane holds feats [8l..8l+7]; W4 k-major in smem (stride 264); butterfly.
// ---------------------------------------------------------------------------
__global__ void __launch_bounds__(256) k_spmm256_w4(const float* __restrict__ bias,
                                                   const float* __restrict__ W4) {
    __shared__ float Ws[16 * 264];   // Ws[c*264 + k] = W4[k*16 + c]
    for (int idx = threadIdx.x; idx < 4096; idx += 256) {
        int k = idx >> 4, c = idx & 15;
        Ws[c * 264 + k] = W4[idx];
    }
    __syncthreads();

    int warp = threadIdx.x >> 5;
    int lane = threadIdx.x & 31;
    int node = blockIdx.x * 8 + warp;
    if (node >= NN) return;

    float acc[8];
    spmm_gather(node, lane, bias, acc);

    float p[16];
    #pragma unroll
    for (int c = 0; c < 16; c++) {
        float4 w0 = *(const float4*)&Ws[c * 264 + 8 * lane];
        float4 w1 = *(const float4*)&Ws[c * 264 + 8 * lane + 4];
        p[c] = acc[0] * w0.x + acc[1] * w0.y + acc[2] * w0.z + acc[3] * w0.w
             + acc[4] * w1.x + acc[5] * w1.y + acc[6] * w1.z + acc[7] * w1.w;
    }
    #pragma unroll
    for (int off = 16; off > 0; off >>= 1)
        #pragma unroll
        for (int c = 0; c < 16; c++)
            p[c] += __shfl_xor_sync(0xffffffffu, p[c], off);

    if (lane < 16)
        g_h4[(size_t)node * 16 + lane] = p[lane];
}

// ---------------------------------------------------------------------------
// SpMM (F=16) + bias + log_softmax -> final output (reads g_h4, fp32)
// ---------------------------------------------------------------------------
__global__ void __launch_bounds__(256) k_spmm16(const float* __restrict__ bias,
                                               float* __restrict__ out) {
    const float* __restrict__ H = g_h4;

    int warp = threadIdx.x >> 5;
    int lane = threadIdx.x & 31;
    int node = blockIdx.x * 8 + warp;
    if (node >= NN) return;

    int f = lane & 15;
    int beg = g_rowptr[node];
    int end = g_rowptr[node + 1];

    float acc = 0.f;
    for (int e = beg; e < end; e++) {
        int2 p = g_edges[e];
        acc += __int_as_float(p.y) * H[(size_t)p.x * 16 + f];
    }
    float di = g_dinv[node];
    acc += di * di * H[(size_t)node * 16 + f];
    acc += bias[f];

    float m = acc;
    #pragma unroll
    for (int o = 8; o > 0; o >>= 1)
        m = fmaxf(m, __shfl_xor_sync(0xffffffffu, m, o, 16));
    float ex = expf(acc - m);
    float s = ex;
    #pragma unroll
    for (int o = 8; o > 0; o >>= 1)
        s += __shfl_xor_sync(0xffffffffu, s, o, 16);

    if (lane < 16)
        out[(size_t)node * 16 + f] = (acc - m) - logf(s);
}

// ---------------------------------------------------------------------------
// Launcher — single stream
// ---------------------------------------------------------------------------
extern "C" void kernel_launch(void* const* d_in, const int* in_sizes, int n_in,
                              void* d_out, int out_size)
{
    const float* x  = (const float*)d_in[0];
    const int*   ei = (const int*)  d_in[1];
    const float* W1 = (const float*)d_in[2];
    const float* b1 = (const float*)d_in[3];
    const float* W2 = (const float*)d_in[4];
    const float* b2 = (const float*)d_in[5];
    const float* W3 = (const float*)d_in[6];
    const float* b3 = (const float*)d_in[7];
    const float* W4 = (const float*)d_in[8];
    const float* b4 = (const float*)d_in[9];
    float* out = (float*)d_out;

    static int s_attr_done = 0;
    if (!s_attr_done) {
        cudaFuncSetAttribute(k_mgemm, cudaFuncAttributeMaxDynamicSharedMemorySize, MG_SMEM);
        s_attr_done = 1;
    }

    const int NB_SCAN = (NN + 1023) / 1024;   // 98
    const int sgrid = (NN + 7) / 8;           // 12500

    // prep: zero(g_deg) + W->fp16 + x->fp16 (independent, one kernel)
    k_prep   <<<26159, 256>>>(x, W1, W2, W3);

    // graph preprocessing
    k_hist   <<<(EE + 255) / 256, 256>>>(ei);
    k_scan1  <<<NB_SCAN, 1024>>>();
    k_scan2  <<<1, 128>>>();
    k_scan3  <<<NB_SCAN, 1024>>>();
    k_scatter<<<(EE + 255) / 256, 256>>>(ei);

    dim3 ggrid(2, MPAD / 128);                // N-split fastest (L2 reuse of A)

    // layer 1
    k_mgemm  <<<ggrid, 256, MG_SMEM>>>(0);
    k_spmm256<<<sgrid, 256>>>(b1);
    // layer 2
    k_mgemm  <<<ggrid, 256, MG_SMEM>>>(1);
    k_spmm256<<<sgrid, 256>>>(b2);
    // layer 3 (+ fused layer-4 linear)
    k_mgemm  <<<ggrid, 256, MG_SMEM>>>(2);
    k_spmm256_w4<<<sgrid, 256>>>(b3, W4);
    // layer 4 aggregate + log_softmax
    k_spmm16 <<<sgrid, 256>>>(b4, out);
}